// round 2
// baseline (speedup 1.0000x reference)
#include <cuda_runtime.h>
#include <math.h>

#define Lq 257
#define Nb 64
#define Dm 768
#define Hh 12
#define HD 64
#define Mrows (Lq * Nb)            // 16448
#define D3 (3 * Dm)                // 2304
#define X_ELEMS ((size_t)Mrows * Dm)                 // 12,632,064
#define W_ELEMS ((size_t)Nb * Hh * Lq * Lq)          // 50,725,632

// ---------------- scratch (device globals; no allocation allowed) ----------
__device__ float g_h[Mrows * Dm];        // ln1 output, reused for ln2 output
__device__ float g_qkv[(size_t)Mrows * D3];
__device__ float g_attn[Mrows * Dm];
__device__ float g_x1[Mrows * Dm];       // x + attn_out

// ---------------- LayerNorm: one block per row, 256 thr, 3 elems/thr -------
__global__ void ln_kernel(const float* __restrict__ x,
                          const float* __restrict__ g,
                          const float* __restrict__ b,
                          float* __restrict__ out) {
    int row = blockIdx.x;
    const float* xr = x + (size_t)row * Dm;
    int tid = threadIdx.x;
    float v0 = xr[tid], v1 = xr[tid + 256], v2 = xr[tid + 512];

    __shared__ float red[256];
    float s = v0 + v1 + v2;
    red[tid] = s; __syncthreads();
    for (int off = 128; off > 0; off >>= 1) {
        if (tid < off) red[tid] += red[tid + off];
        __syncthreads();
    }
    float mu = red[0] * (1.0f / Dm);
    __syncthreads();

    float d0 = v0 - mu, d1 = v1 - mu, d2 = v2 - mu;
    red[tid] = d0 * d0 + d1 * d1 + d2 * d2; __syncthreads();
    for (int off = 128; off > 0; off >>= 1) {
        if (tid < off) red[tid] += red[tid + off];
        __syncthreads();
    }
    float rstd = rsqrtf(red[0] * (1.0f / Dm) + 1e-5f);

    float* orow = out + (size_t)row * Dm;
    orow[tid]       = d0 * rstd * g[tid]       + b[tid];
    orow[tid + 256] = d1 * rstd * g[tid + 256] + b[tid + 256];
    orow[tid + 512] = d2 * rstd * g[tid + 512] + b[tid + 512];
}

// ---------------- GEMM NT: C[M,Nc] = A[M,K] * B[Nc,K]^T (+epilogue) --------
// BM=64, BN=128, BK=16, 256 threads, 4x8 per-thread tile.
// EPI: 0 = plain, 1 = +bias, 2 = +bias +res, 3 = res + quickGELU(C+bias)
template <int EPI>
__global__ void gemm_nt(const float* __restrict__ A,
                        const float* __restrict__ B,
                        const float* __restrict__ bias,
                        const float* __restrict__ res,
                        float* __restrict__ C,
                        int K, int Nc) {
    __shared__ float As[64][17];
    __shared__ float Bs[128][17];
    const int mBase = blockIdx.y * 64;
    const int nBase = blockIdx.x * 128;
    const int t  = threadIdx.x;
    const int ty = t >> 4;           // 0..15
    const int tx = t & 15;           // 0..15

    float acc[4][8];
#pragma unroll
    for (int i = 0; i < 4; i++)
#pragma unroll
        for (int j = 0; j < 8; j++) acc[i][j] = 0.0f;

    const int ar  = t >> 2;          // 0..63
    const int akc = (t & 3) * 4;     // 0,4,8,12

    for (int k0 = 0; k0 < K; k0 += 16) {
        // A tile: 64x16, one float4 per thread
        {
            float4 v = *(const float4*)(A + (size_t)(mBase + ar) * K + k0 + akc);
            As[ar][akc] = v.x; As[ar][akc+1] = v.y; As[ar][akc+2] = v.z; As[ar][akc+3] = v.w;
        }
        // B tile: 128x16, two float4 per thread
#pragma unroll
        for (int rep = 0; rep < 2; rep++) {
            int idx = t + rep * 256;
            int br = idx >> 2, bkc = (idx & 3) * 4;
            float4 v = *(const float4*)(B + (size_t)(nBase + br) * K + k0 + bkc);
            Bs[br][bkc] = v.x; Bs[br][bkc+1] = v.y; Bs[br][bkc+2] = v.z; Bs[br][bkc+3] = v.w;
        }
        __syncthreads();
#pragma unroll
        for (int k = 0; k < 16; k++) {
            float a[4], bb[8];
#pragma unroll
            for (int i = 0; i < 4; i++) a[i] = As[ty * 4 + i][k];
#pragma unroll
            for (int j = 0; j < 8; j++) bb[j] = Bs[tx * 8 + j][k];
#pragma unroll
            for (int i = 0; i < 4; i++)
#pragma unroll
                for (int j = 0; j < 8; j++) acc[i][j] = fmaf(a[i], bb[j], acc[i][j]);
        }
        __syncthreads();
    }

#pragma unroll
    for (int i = 0; i < 4; i++) {
        int row = mBase + ty * 4 + i;
#pragma unroll
        for (int j = 0; j < 8; j++) {
            int col = nBase + tx * 8 + j;
            float v = acc[i][j];
            if (EPI >= 1) v += bias[col];
            if (EPI == 2) v += res[(size_t)row * Nc + col];
            if (EPI == 3) {
                float sg = 1.0f / (1.0f + expf(-1.702f * v));
                v = res[(size_t)row * Nc + col] + v * sg;
            }
            C[(size_t)row * Nc + col] = v;
        }
    }
}

// ---------------- attention scores: w[n,h,l,m] = scale * q.k ---------------
// grid: (mTiles=9, lTiles=9, N*H); block 256
__global__ void scores_kernel(const float* __restrict__ qkv, float* __restrict__ w) {
    const int nh = blockIdx.z;
    const int n = nh / Hh, h = nh % Hh;
    const int lBase = blockIdx.y * 32;
    const int mBase = blockIdx.x * 32;
    const int t = threadIdx.x;

    __shared__ float Qs[32][65];
    __shared__ float Ks[32][65];

    const size_t qoff = (size_t)h * HD;            // within qkv row
    const size_t koff = (size_t)Dm + h * HD;

    // load tiles: each thread 8 floats (2 float4) per tile
    {
        int r = t >> 3, c = (t & 7) * 8;
        int lg = lBase + r;
        if (lg < Lq) {
            const float* p = qkv + ((size_t)lg * Nb + n) * D3 + qoff + c;
            float4 v0 = *(const float4*)p;
            float4 v1 = *(const float4*)(p + 4);
            Qs[r][c]   = v0.x; Qs[r][c+1] = v0.y; Qs[r][c+2] = v0.z; Qs[r][c+3] = v0.w;
            Qs[r][c+4] = v1.x; Qs[r][c+5] = v1.y; Qs[r][c+6] = v1.z; Qs[r][c+7] = v1.w;
        } else {
#pragma unroll
            for (int u = 0; u < 8; u++) Qs[r][c + u] = 0.0f;
        }
        int mg = mBase + r;
        if (mg < Lq) {
            const float* p = qkv + ((size_t)mg * Nb + n) * D3 + koff + c;
            float4 v0 = *(const float4*)p;
            float4 v1 = *(const float4*)(p + 4);
            Ks[r][c]   = v0.x; Ks[r][c+1] = v0.y; Ks[r][c+2] = v0.z; Ks[r][c+3] = v0.w;
            Ks[r][c+4] = v1.x; Ks[r][c+5] = v1.y; Ks[r][c+6] = v1.z; Ks[r][c+7] = v1.w;
        } else {
#pragma unroll
            for (int u = 0; u < 8; u++) Ks[r][c + u] = 0.0f;
        }
    }
    __syncthreads();

    const int ty = t >> 4, tx = t & 15;     // 2x2 outputs per thread
    float a00 = 0, a01 = 0, a10 = 0, a11 = 0;
#pragma unroll
    for (int k = 0; k < 64; k++) {
        float q0 = Qs[ty * 2][k],     q1 = Qs[ty * 2 + 1][k];
        float k0 = Ks[tx * 2][k],     k1 = Ks[tx * 2 + 1][k];
        a00 = fmaf(q0, k0, a00); a01 = fmaf(q0, k1, a01);
        a10 = fmaf(q1, k0, a10); a11 = fmaf(q1, k1, a11);
    }
    const float scale = 0.125f; // 1/sqrt(64)
    int l0 = lBase + ty * 2, m0 = mBase + tx * 2;
    if (l0 < Lq) {
        float* row = w + ((size_t)nh * Lq + l0) * Lq;
        if (m0     < Lq) row[m0]     = a00 * scale;
        if (m0 + 1 < Lq) row[m0 + 1] = a01 * scale;
    }
    if (l0 + 1 < Lq) {
        float* row = w + ((size_t)nh * Lq + l0 + 1) * Lq;
        if (m0     < Lq) row[m0]     = a10 * scale;
        if (m0 + 1 < Lq) row[m0 + 1] = a11 * scale;
    }
}

// ---------------- softmax in place over last dim (length 257) --------------
__global__ void softmax_kernel(float* __restrict__ w) {
    float* p = w + (size_t)blockIdx.x * Lq;
    int tid = threadIdx.x;
    float a = p[tid];                                 // tid < 256 < 257 always valid
    float b = (tid + 256 < Lq) ? p[tid + 256] : -INFINITY;

    __shared__ float red[256];
    red[tid] = fmaxf(a, b); __syncthreads();
    for (int off = 128; off > 0; off >>= 1) {
        if (tid < off) red[tid] = fmaxf(red[tid], red[tid + off]);
        __syncthreads();
    }
    float mx = red[0]; __syncthreads();

    float ea = expf(a - mx);
    float eb = (tid + 256 < Lq) ? expf(b - mx) : 0.0f;
    red[tid] = ea + eb; __syncthreads();
    for (int off = 128; off > 0; off >>= 1) {
        if (tid < off) red[tid] += red[tid + off];
        __syncthreads();
    }
    float inv = 1.0f / red[0];
    p[tid] = ea * inv;
    if (tid + 256 < Lq) p[tid + 256] = eb * inv;
}

// ---------------- attn = weights @ V : out[l,n,h,:] ------------------------
// grid: (lTiles=9, N*H); block 256; each thread: 1 l-row, 8 hd cols
__global__ void attnv_kernel(const float* __restrict__ w,
                             const float* __restrict__ qkv,
                             float* __restrict__ out) {
    const int nh = blockIdx.y;
    const int n = nh / Hh, h = nh % Hh;
    const int lBase = blockIdx.x * 32;
    const int t = threadIdx.x;
    const int l_local  = t & 31;         // lane id -> row (conflict-free Ws read)
    const int hd_base  = (t >> 5) * 8;   // warp id -> hd chunk

    __shared__ float Ws[32][33];
    __shared__ float Vs[32][64];

    const size_t voff = (size_t)2 * Dm + h * HD;
    float acc[8];
#pragma unroll
    for (int j = 0; j < 8; j++) acc[j] = 0.0f;

    for (int m0 = 0; m0 < Lq; m0 += 32) {
        // Ws: 32 l x 32 m, 4 scalars per thread (guarded)
        {
            int r = t >> 3, c = (t & 7) * 4;
            int lg = lBase + r;
#pragma unroll
            for (int u = 0; u < 4; u++) {
                int mg = m0 + c + u;
                Ws[r][c + u] = (lg < Lq && mg < Lq)
                    ? w[((size_t)nh * Lq + lg) * Lq + mg] : 0.0f;
            }
        }
        // Vs: 32 m x 64 hd, 8 floats per thread
        {
            int r = t >> 3, c = (t & 7) * 8;
            int mg = m0 + r;
            if (mg < Lq) {
                const float* p = qkv + ((size_t)mg * Nb + n) * D3 + voff + c;
                float4 v0 = *(const float4*)p;
                float4 v1 = *(const float4*)(p + 4);
                Vs[r][c]   = v0.x; Vs[r][c+1] = v0.y; Vs[r][c+2] = v0.z; Vs[r][c+3] = v0.w;
                Vs[r][c+4] = v1.x; Vs[r][c+5] = v1.y; Vs[r][c+6] = v1.z; Vs[r][c+7] = v1.w;
            } else {
#pragma unroll
                for (int u = 0; u < 8; u++) Vs[r][c + u] = 0.0f;
            }
        }
        __syncthreads();
#pragma unroll
        for (int m = 0; m < 32; m++) {
            float wv = Ws[l_local][m];
#pragma unroll
            for (int j = 0; j < 8; j++)
                acc[j] = fmaf(wv, Vs[m][hd_base + j], acc[j]);
        }
        __syncthreads();
    }

    int lg = lBase + l_local;
    if (lg < Lq) {
        float* p = out + ((size_t)lg * Nb + n) * Dm + h * HD + hd_base;
#pragma unroll
        for (int j = 0; j < 8; j++) p[j] = acc[j];
    }
}

// ---------------------------------------------------------------------------
extern "C" void kernel_launch(void* const* d_in, const int* in_sizes, int n_in,
                              void* d_out, int out_size) {
    const float* x          = (const float*)d_in[0];
    const float* in_proj_w  = (const float*)d_in[1];
    const float* in_proj_b  = (const float*)d_in[2];
    const float* out_proj_w = (const float*)d_in[3];
    const float* out_proj_b = (const float*)d_in[4];
    const float* ln1_g      = (const float*)d_in[5];
    const float* ln1_b      = (const float*)d_in[6];
    const float* ln2_g      = (const float*)d_in[7];
    const float* ln2_b      = (const float*)d_in[8];
    const float* fc_w       = (const float*)d_in[9];
    const float* fc_b       = (const float*)d_in[10];

    float* out_x = (float*)d_out;                 // [L,N,D]
    float* out_w = (float*)d_out + X_ELEMS;       // [N,H,L,L]

    float* h    = g_h;
    float* qkv  = g_qkv;
    float* attn = g_attn;
    float* x1   = g_x1;

    // 1) LN1
    ln_kernel<<<Mrows, 256>>>(x, ln1_g, ln1_b, h);

    // 2) qkv = h @ W_in^T + b  : [16448, 2304]
    {
        dim3 grid(D3 / 128, Mrows / 64);
        gemm_nt<1><<<grid, 256>>>(h, in_proj_w, in_proj_b, nullptr, qkv, Dm, D3);
    }

    // 3) scores -> out_w (pre-softmax)
    {
        dim3 grid((Lq + 31) / 32, (Lq + 31) / 32, Nb * Hh);
        scores_kernel<<<grid, 256>>>(qkv, out_w);
    }

    // 4) softmax in place (this is the weights output)
    softmax_kernel<<<Nb * Hh * Lq, 256>>>(out_w);

    // 5) attn = weights @ V
    {
        dim3 grid((Lq + 31) / 32, Nb * Hh);
        attnv_kernel<<<grid, 256>>>(out_w, qkv, attn);
    }

    // 6) x1 = x + attn @ W_out^T + b
    {
        dim3 grid(Dm / 128, Mrows / 64);
        gemm_nt<2><<<grid, 256>>>(attn, out_proj_w, out_proj_b, x, x1, Dm, Dm);
    }

    // 7) LN2 (reuse h buffer)
    ln_kernel<<<Mrows, 256>>>(x1, ln2_g, ln2_b, h);

    // 8) out_x = x1 + quick_gelu(h @ fc_w^T + fc_b)
    {
        dim3 grid(Dm / 128, Mrows / 64);
        gemm_nt<3><<<grid, 256>>>(h, fc_w, fc_b, x1, out_x, Dm, Dm);
    }
}

// round 5
// speedup vs baseline: 1.1525x; 1.1525x over previous
#include <cuda_runtime.h>
#include <math.h>
#include <stdint.h>

#define Lq 257
#define Nb 64
#define Dm 768
#define Hh 12
#define HD 64
#define Mrows (Lq * Nb)            // 16448
#define D3 (3 * Dm)                // 2304
#define X_ELEMS ((size_t)Mrows * Dm)
#define W_ELEMS ((size_t)Nb * Hh * Lq * Lq)

// ---------------- scratch (device globals; no allocation allowed) ----------
__device__ float g_h[Mrows * Dm];
__device__ float g_qkv[(size_t)Mrows * D3];
__device__ float g_attn[Mrows * Dm];
__device__ float g_x1[Mrows * Dm];

// ---------------- PTX helpers ----------------------------------------------
__device__ __forceinline__ uint32_t f2tf(float f) {
    uint32_t r;
    asm("cvt.rna.tf32.f32 %0, %1;" : "=r"(r) : "f"(f));
    return r;
}
__device__ __forceinline__ void mma_tf32(float* c, const uint32_t* a, const uint32_t* b) {
    asm volatile(
        "mma.sync.aligned.m16n8k8.row.col.f32.tf32.tf32.f32 "
        "{%0,%1,%2,%3}, {%4,%5,%6,%7}, {%8,%9}, {%0,%1,%2,%3};\n"
        : "+f"(c[0]), "+f"(c[1]), "+f"(c[2]), "+f"(c[3])
        : "r"(a[0]), "r"(a[1]), "r"(a[2]), "r"(a[3]), "r"(b[0]), "r"(b[1]));
}
__device__ __forceinline__ void cp_async16(void* smem, const void* gmem) {
    uint32_t s = (uint32_t)__cvta_generic_to_shared(smem);
    asm volatile("cp.async.ca.shared.global [%0], [%1], 16;\n" :: "r"(s), "l"(gmem));
}
__device__ __forceinline__ void cp_commit() {
    asm volatile("cp.async.commit_group;\n");
}
__device__ __forceinline__ void cp_wait1() {
    asm volatile("cp.async.wait_group 1;\n");
}

// ---------------- LayerNorm ------------------------------------------------
__global__ void ln_kernel(const float* __restrict__ x,
                          const float* __restrict__ g,
                          const float* __restrict__ b,
                          float* __restrict__ out) {
    int row = blockIdx.x;
    const float* xr = x + (size_t)row * Dm;
    int tid = threadIdx.x;
    float v0 = xr[tid], v1 = xr[tid + 256], v2 = xr[tid + 512];

    __shared__ float red[256];
    red[tid] = v0 + v1 + v2; __syncthreads();
    for (int off = 128; off > 0; off >>= 1) {
        if (tid < off) red[tid] += red[tid + off];
        __syncthreads();
    }
    float mu = red[0] * (1.0f / Dm);
    __syncthreads();

    float d0 = v0 - mu, d1 = v1 - mu, d2 = v2 - mu;
    red[tid] = d0 * d0 + d1 * d1 + d2 * d2; __syncthreads();
    for (int off = 128; off > 0; off >>= 1) {
        if (tid < off) red[tid] += red[tid + off];
        __syncthreads();
    }
    float rstd = rsqrtf(red[0] * (1.0f / Dm) + 1e-5f);

    float* orow = out + (size_t)row * Dm;
    orow[tid]       = d0 * rstd * g[tid]       + b[tid];
    orow[tid + 256] = d1 * rstd * g[tid + 256] + b[tid + 256];
    orow[tid + 512] = d2 * rstd * g[tid + 512] + b[tid + 512];
}

// ---------------- TF32 tensor-core GEMM NT ---------------------------------
// C[M,Nc] = A[M,K] * B[Nc,K]^T (+epilogue). BM=128, BN=128, BK=16.
// 256 threads = 8 warps, warp tile 64x32 (4 m16 x 4 n8 mma tiles).
// Smem rows padded to 20 words (80B, 16B-aligned) -> conflict-free frag LDS.
// EPI: 1 = +bias, 2 = +bias +res, 3 = res + quickGELU(C+bias)
#define SROW 20
template <int EPI>
__global__ void __launch_bounds__(256) gemm_tc(const float* __restrict__ A,
                                               const float* __restrict__ B,
                                               const float* __restrict__ bias,
                                               const float* __restrict__ res,
                                               float* __restrict__ C,
                                               int K, int Nc, int M) {
    __shared__ float As[2][128 * SROW];
    __shared__ float Bs[2][128 * SROW];

    const int t = threadIdx.x;
    const int wid = t >> 5, lane = t & 31;
    const int wm = wid >> 2, wn = wid & 3;       // 2 x 4 warp grid
    const int g = lane >> 2, tq = lane & 3;
    const int mBase = blockIdx.y * 128;
    const int nBase = blockIdx.x * 128;

    float acc[4][4][4];
#pragma unroll
    for (int i = 0; i < 4; i++)
#pragma unroll
        for (int j = 0; j < 4; j++)
#pragma unroll
            for (int q = 0; q < 4; q++) acc[i][j][q] = 0.0f;

    // per-thread load coords: 2 chunks of 16B per matrix per tile
    const int lr0 = t >> 2, lc0 = (t & 3) * 4;       // rows 0..63
    const int lr1 = lr0 + 64;

    int arow0 = mBase + lr0; if (arow0 >= M) arow0 = M - 1;
    int arow1 = mBase + lr1; if (arow1 >= M) arow1 = M - 1;
    const float* a0p = A + (size_t)arow0 * K + lc0;
    const float* a1p = A + (size_t)arow1 * K + lc0;
    const float* b0p = B + (size_t)(nBase + lr0) * K + lc0;
    const float* b1p = B + (size_t)(nBase + lr1) * K + lc0;

    const int T = K / 16;

#define LOAD_TILE(stage, k0)                                                  \
    do {                                                                      \
        cp_async16(&As[stage][lr0 * SROW + lc0], a0p + (k0));                 \
        cp_async16(&As[stage][lr1 * SROW + lc0], a1p + (k0));                 \
        cp_async16(&Bs[stage][lr0 * SROW + lc0], b0p + (k0));                 \
        cp_async16(&Bs[stage][lr1 * SROW + lc0], b1p + (k0));                 \
    } while (0)

    LOAD_TILE(0, 0);
    cp_commit();

    for (int tile = 0; tile < T; tile++) {
        if (tile + 1 < T) LOAD_TILE((tile + 1) & 1, (tile + 1) * 16);
        cp_commit();
        cp_wait1();
        __syncthreads();

        const float* as = As[tile & 1];
        const float* bs = Bs[tile & 1];

#pragma unroll
        for (int ks = 0; ks < 2; ks++) {
            uint32_t af[4][4];
#pragma unroll
            for (int mt = 0; mt < 4; mt++) {
                int m0 = wm * 64 + mt * 16;
                int kk = ks * 8 + tq;
                af[mt][0] = f2tf(as[(m0 + g)     * SROW + kk]);
                af[mt][1] = f2tf(as[(m0 + g + 8) * SROW + kk]);
                af[mt][2] = f2tf(as[(m0 + g)     * SROW + kk + 4]);
                af[mt][3] = f2tf(as[(m0 + g + 8) * SROW + kk + 4]);
            }
            uint32_t bf[4][2];
#pragma unroll
            for (int nt = 0; nt < 4; nt++) {
                int n0 = wn * 32 + nt * 8;
                int kk = ks * 8 + tq;
                bf[nt][0] = f2tf(bs[(n0 + g) * SROW + kk]);
                bf[nt][1] = f2tf(bs[(n0 + g) * SROW + kk + 4]);
            }
#pragma unroll
            for (int mt = 0; mt < 4; mt++)
#pragma unroll
                for (int nt = 0; nt < 4; nt++)
                    mma_tf32(acc[mt][nt], af[mt], bf[nt]);
        }
        __syncthreads();
    }

    // epilogue
#pragma unroll
    for (int mt = 0; mt < 4; mt++) {
        int r0 = mBase + wm * 64 + mt * 16 + g;
        int r1 = r0 + 8;
#pragma unroll
        for (int nt = 0; nt < 4; nt++) {
            int col = nBase + wn * 32 + nt * 8 + 2 * tq;
            float bv0 = bias[col], bv1 = bias[col + 1];
#pragma unroll
            for (int half = 0; half < 2; half++) {
                int row = half ? r1 : r0;
                if (row >= M) continue;
                float v0 = acc[mt][nt][half * 2]     + bv0;
                float v1 = acc[mt][nt][half * 2 + 1] + bv1;
                size_t off = (size_t)row * Nc + col;
                if (EPI == 2) {
                    v0 += res[off]; v1 += res[off + 1];
                } else if (EPI == 3) {
                    float s0 = 1.0f / (1.0f + expf(-1.702f * v0));
                    float s1 = 1.0f / (1.0f + expf(-1.702f * v1));
                    v0 = res[off]     + v0 * s0;
                    v1 = res[off + 1] + v1 * s1;
                }
                C[off]     = v0;
                C[off + 1] = v1;
            }
        }
    }
}
#undef LOAD_TILE
#undef SROW

// ---------------- attention scores (fp32, protects weights precision) ------
__global__ void scores_kernel(const float* __restrict__ qkv, float* __restrict__ w) {
    const int nh = blockIdx.z;
    const int n = nh / Hh, h = nh % Hh;
    const int lBase = blockIdx.y * 32;
    const int mBase = blockIdx.x * 32;
    const int t = threadIdx.x;

    __shared__ float Qs[32][65];
    __shared__ float Ks[32][65];

    const size_t qoff = (size_t)h * HD;
    const size_t koff = (size_t)Dm + h * HD;

    {
        int r = t >> 3, c = (t & 7) * 8;
        int lg = lBase + r;
        if (lg < Lq) {
            const float* p = qkv + ((size_t)lg * Nb + n) * D3 + qoff + c;
            float4 v0 = *(const float4*)p;
            float4 v1 = *(const float4*)(p + 4);
            Qs[r][c]   = v0.x; Qs[r][c+1] = v0.y; Qs[r][c+2] = v0.z; Qs[r][c+3] = v0.w;
            Qs[r][c+4] = v1.x; Qs[r][c+5] = v1.y; Qs[r][c+6] = v1.z; Qs[r][c+7] = v1.w;
        } else {
#pragma unroll
            for (int u = 0; u < 8; u++) Qs[r][c + u] = 0.0f;
        }
        int mg = mBase + r;
        if (mg < Lq) {
            const float* p = qkv + ((size_t)mg * Nb + n) * D3 + koff + c;
            float4 v0 = *(const float4*)p;
            float4 v1 = *(const float4*)(p + 4);
            Ks[r][c]   = v0.x; Ks[r][c+1] = v0.y; Ks[r][c+2] = v0.z; Ks[r][c+3] = v0.w;
            Ks[r][c+4] = v1.x; Ks[r][c+5] = v1.y; Ks[r][c+6] = v1.z; Ks[r][c+7] = v1.w;
        } else {
#pragma unroll
            for (int u = 0; u < 8; u++) Ks[r][c + u] = 0.0f;
        }
    }
    __syncthreads();

    const int ty = t >> 4, tx = t & 15;
    float a00 = 0, a01 = 0, a10 = 0, a11 = 0;
#pragma unroll
    for (int k = 0; k < 64; k++) {
        float q0 = Qs[ty * 2][k], q1 = Qs[ty * 2 + 1][k];
        float k0 = Ks[tx * 2][k], k1 = Ks[tx * 2 + 1][k];
        a00 = fmaf(q0, k0, a00); a01 = fmaf(q0, k1, a01);
        a10 = fmaf(q1, k0, a10); a11 = fmaf(q1, k1, a11);
    }
    const float scale = 0.125f;
    int l0 = lBase + ty * 2, m0 = mBase + tx * 2;
    if (l0 < Lq) {
        float* row = w + ((size_t)nh * Lq + l0) * Lq;
        if (m0     < Lq) row[m0]     = a00 * scale;
        if (m0 + 1 < Lq) row[m0 + 1] = a01 * scale;
    }
    if (l0 + 1 < Lq) {
        float* row = w + ((size_t)nh * Lq + l0 + 1) * Lq;
        if (m0     < Lq) row[m0]     = a10 * scale;
        if (m0 + 1 < Lq) row[m0 + 1] = a11 * scale;
    }
}

// ---------------- softmax: one warp per row, shuffle reductions ------------
__global__ void softmax_warp(float* __restrict__ w, int rows) {
    int warp = (blockIdx.x * blockDim.x + threadIdx.x) >> 5;
    if (warp >= rows) return;
    int lane = threadIdx.x & 31;
    float* p = w + (size_t)warp * Lq;

    float v[9];
#pragma unroll
    for (int i = 0; i < 9; i++) {
        int idx = lane + i * 32;
        v[i] = (idx < Lq) ? p[idx] : -INFINITY;
    }
    float mx = v[0];
#pragma unroll
    for (int i = 1; i < 9; i++) mx = fmaxf(mx, v[i]);
#pragma unroll
    for (int off = 16; off > 0; off >>= 1)
        mx = fmaxf(mx, __shfl_xor_sync(0xffffffffu, mx, off));

    float s = 0.0f;
#pragma unroll
    for (int i = 0; i < 9; i++) {
        v[i] = (lane + i * 32 < Lq) ? expf(v[i] - mx) : 0.0f;
        s += v[i];
    }
#pragma unroll
    for (int off = 16; off > 0; off >>= 1)
        s += __shfl_xor_sync(0xffffffffu, s, off);
    float inv = 1.0f / s;
#pragma unroll
    for (int i = 0; i < 9; i++) {
        int idx = lane + i * 32;
        if (idx < Lq) p[idx] = v[i] * inv;
    }
}

// ---------------- attn = weights @ V ---------------------------------------
__global__ void attnv_kernel(const float* __restrict__ w,
                             const float* __restrict__ qkv,
                             float* __restrict__ out) {
    const int nh = blockIdx.y;
    const int n = nh / Hh, h = nh % Hh;
    const int lBase = blockIdx.x * 32;
    const int t = threadIdx.x;
    const int l_local = t & 31;
    const int hd_base = (t >> 5) * 8;

    __shared__ float Ws[32][33];
    __shared__ float Vs[32][64];

    const size_t voff = (size_t)2 * Dm + h * HD;
    float acc[8];
#pragma unroll
    for (int j = 0; j < 8; j++) acc[j] = 0.0f;

    for (int m0 = 0; m0 < Lq; m0 += 32) {
        {
            int r = t >> 3, c = (t & 7) * 4;
            int lg = lBase + r;
#pragma unroll
            for (int u = 0; u < 4; u++) {
                int mg = m0 + c + u;
                Ws[r][c + u] = (lg < Lq && mg < Lq)
                    ? w[((size_t)nh * Lq + lg) * Lq + mg] : 0.0f;
            }
        }
        {
            int r = t >> 3, c = (t & 7) * 8;
            int mg = m0 + r;
            if (mg < Lq) {
                const float* p = qkv + ((size_t)mg * Nb + n) * D3 + voff + c;
                float4 v0 = *(const float4*)p;
                float4 v1 = *(const float4*)(p + 4);
                Vs[r][c]   = v0.x; Vs[r][c+1] = v0.y; Vs[r][c+2] = v0.z; Vs[r][c+3] = v0.w;
                Vs[r][c+4] = v1.x; Vs[r][c+5] = v1.y; Vs[r][c+6] = v1.z; Vs[r][c+7] = v1.w;
            } else {
#pragma unroll
                for (int u = 0; u < 8; u++) Vs[r][c + u] = 0.0f;
            }
        }
        __syncthreads();
#pragma unroll
        for (int m = 0; m < 32; m++) {
            float wv = Ws[l_local][m];
#pragma unroll
            for (int j = 0; j < 8; j++)
                acc[j] = fmaf(wv, Vs[m][hd_base + j], acc[j]);
        }
        __syncthreads();
    }

    int lg = lBase + l_local;
    if (lg < Lq) {
        float* p = out + ((size_t)lg * Nb + n) * Dm + h * HD + hd_base;
#pragma unroll
        for (int j = 0; j < 8; j++) p[j] = acc[j];
    }
}

// ---------------------------------------------------------------------------
extern "C" void kernel_launch(void* const* d_in, const int* in_sizes, int n_in,
                              void* d_out, int out_size) {
    const float* x          = (const float*)d_in[0];
    const float* in_proj_w  = (const float*)d_in[1];
    const float* in_proj_b  = (const float*)d_in[2];
    const float* out_proj_w = (const float*)d_in[3];
    const float* out_proj_b = (const float*)d_in[4];
    const float* ln1_g      = (const float*)d_in[5];
    const float* ln1_b      = (const float*)d_in[6];
    const float* ln2_g      = (const float*)d_in[7];
    const float* ln2_b      = (const float*)d_in[8];
    const float* fc_w       = (const float*)d_in[9];
    const float* fc_b       = (const float*)d_in[10];

    float* out_x = (float*)d_out;
    float* out_w = (float*)d_out + X_ELEMS;

    float* h    = g_h;
    float* qkv  = g_qkv;
    float* attn = g_attn;
    float* x1   = g_x1;

    const int mGrid = (Mrows + 127) / 128;   // 129

    // 1) LN1
    ln_kernel<<<Mrows, 256>>>(x, ln1_g, ln1_b, h);

    // 2) qkv = h @ W_in^T + b
    {
        dim3 grid(D3 / 128, mGrid);
        gemm_tc<1><<<grid, 256>>>(h, in_proj_w, in_proj_b, nullptr, qkv, Dm, D3, Mrows);
    }

    // 3) scores -> out_w (pre-softmax)
    {
        dim3 grid((Lq + 31) / 32, (Lq + 31) / 32, Nb * Hh);
        scores_kernel<<<grid, 256>>>(qkv, out_w);
    }

    // 4) softmax in place (weights output)
    {
        int rows = Nb * Hh * Lq;
        int warpsPerBlock = 8;
        int blocks = (rows + warpsPerBlock - 1) / warpsPerBlock;
        softmax_warp<<<blocks, warpsPerBlock * 32>>>(out_w, rows);
    }

    // 5) attn = weights @ V
    {
        dim3 grid((Lq + 31) / 32, Nb * Hh);
        attnv_kernel<<<grid, 256>>>(out_w, qkv, attn);
    }

    // 6) x1 = x + attn @ W_out^T + b
    {
        dim3 grid(Dm / 128, mGrid);
        gemm_tc<2><<<grid, 256>>>(attn, out_proj_w, out_proj_b, x, x1, Dm, Dm, Mrows);
    }

    // 7) LN2
    ln_kernel<<<Mrows, 256>>>(x1, ln2_g, ln2_b, h);

    // 8) out = x1 + quick_gelu(h @ fc_w^T + fc_b)
    {
        dim3 grid(Dm / 128, mGrid);
        gemm_tc<3><<<grid, 256>>>(h, fc_w, fc_b, x1, out_x, Dm, Dm, Mrows);
    }
}

// round 8
// speedup vs baseline: 1.4021x; 1.2166x over previous
#include <cuda_runtime.h>
#include <math.h>
#include <stdint.h>

#define Lq 257
#define Nb 64
#define Dm 768
#define Hh 12
#define HD 64
#define NH (Nb * Hh)               // 768 heads total
#define Mrows (Lq * Nb)            // 16448
#define D3 (3 * Dm)                // 2304
#define LHD (Lq * HD)              // 16448 floats per head per tensor
#define X_ELEMS ((size_t)Mrows * Dm)

// ---------------- scratch (device globals; no allocation allowed) ----------
__device__ float g_h[Mrows * Dm];
__device__ float g_qkv[(size_t)Mrows * D3];   // head-major: [which][nh][l][hd]
__device__ float g_attn[Mrows * Dm];
__device__ float g_x1[Mrows * Dm];

// ---------------- PTX helpers ----------------------------------------------
__device__ __forceinline__ uint32_t f2tf(float f) {
    uint32_t r;
    asm("cvt.rna.tf32.f32 %0, %1;" : "=r"(r) : "f"(f));
    return r;
}
__device__ __forceinline__ void mma_tf32(float* c, const uint32_t* a, const uint32_t* b) {
    asm volatile(
        "mma.sync.aligned.m16n8k8.row.col.f32.tf32.tf32.f32 "
        "{%0,%1,%2,%3}, {%4,%5,%6,%7}, {%8,%9}, {%0,%1,%2,%3};\n"
        : "+f"(c[0]), "+f"(c[1]), "+f"(c[2]), "+f"(c[3])
        : "r"(a[0]), "r"(a[1]), "r"(a[2]), "r"(a[3]), "r"(b[0]), "r"(b[1]));
}
__device__ __forceinline__ void cp_async16(void* smem, const void* gmem) {
    uint32_t s = (uint32_t)__cvta_generic_to_shared(smem);
    asm volatile("cp.async.ca.shared.global [%0], [%1], 16;\n" :: "r"(s), "l"(gmem));
}
__device__ __forceinline__ void cp_commit() { asm volatile("cp.async.commit_group;\n"); }
__device__ __forceinline__ void cp_wait1()  { asm volatile("cp.async.wait_group 1;\n"); }

// ---------------- LayerNorm ------------------------------------------------
__global__ void ln_kernel(const float* __restrict__ x,
                          const float* __restrict__ g,
                          const float* __restrict__ b,
                          float* __restrict__ out) {
    int row = blockIdx.x;
    const float* xr = x + (size_t)row * Dm;
    int tid = threadIdx.x;
    float v0 = xr[tid], v1 = xr[tid + 256], v2 = xr[tid + 512];

    __shared__ float red[256];
    red[tid] = v0 + v1 + v2; __syncthreads();
    for (int off = 128; off > 0; off >>= 1) {
        if (tid < off) red[tid] += red[tid + off];
        __syncthreads();
    }
    float mu = red[0] * (1.0f / Dm);
    __syncthreads();

    float d0 = v0 - mu, d1 = v1 - mu, d2 = v2 - mu;
    red[tid] = d0 * d0 + d1 * d1 + d2 * d2; __syncthreads();
    for (int off = 128; off > 0; off >>= 1) {
        if (tid < off) red[tid] += red[tid + off];
        __syncthreads();
    }
    float rstd = rsqrtf(red[0] * (1.0f / Dm) + 1e-5f);

    float* orow = out + (size_t)row * Dm;
    orow[tid]       = d0 * rstd * g[tid]       + b[tid];
    orow[tid + 256] = d1 * rstd * g[tid + 256] + b[tid + 256];
    orow[tid + 512] = d2 * rstd * g[tid + 512] + b[tid + 512];
}

// ---------------- TF32 tensor-core GEMM NT ---------------------------------
// C[M,Nc] = A[M,K] * B[Nc,K]^T (+epilogue). BM=128, BN=128, BK=16.
// EPI: 1 = +bias, 2 = +bias +res, 3 = res + quickGELU(C+bias),
//      4 = +bias then scatter into head-major QKV layout
#define SROW 20
template <int EPI>
__global__ void __launch_bounds__(256) gemm_tc(const float* __restrict__ A,
                                               const float* __restrict__ B,
                                               const float* __restrict__ bias,
                                               const float* __restrict__ res,
                                               float* __restrict__ C,
                                               int K, int Nc, int M) {
    __shared__ float As[2][128 * SROW];
    __shared__ float Bs[2][128 * SROW];

    const int t = threadIdx.x;
    const int wid = t >> 5, lane = t & 31;
    const int wm = wid >> 2, wn = wid & 3;
    const int g = lane >> 2, tq = lane & 3;
    const int mBase = blockIdx.y * 128;
    const int nBase = blockIdx.x * 128;

    float acc[4][4][4];
#pragma unroll
    for (int i = 0; i < 4; i++)
#pragma unroll
        for (int j = 0; j < 4; j++)
#pragma unroll
            for (int q = 0; q < 4; q++) acc[i][j][q] = 0.0f;

    const int lr0 = t >> 2, lc0 = (t & 3) * 4;
    const int lr1 = lr0 + 64;

    int arow0 = mBase + lr0; if (arow0 >= M) arow0 = M - 1;
    int arow1 = mBase + lr1; if (arow1 >= M) arow1 = M - 1;
    const float* a0p = A + (size_t)arow0 * K + lc0;
    const float* a1p = A + (size_t)arow1 * K + lc0;
    const float* b0p = B + (size_t)(nBase + lr0) * K + lc0;
    const float* b1p = B + (size_t)(nBase + lr1) * K + lc0;

    const int T = K / 16;

#define LOAD_TILE(stage, k0)                                                  \
    do {                                                                      \
        cp_async16(&As[stage][lr0 * SROW + lc0], a0p + (k0));                 \
        cp_async16(&As[stage][lr1 * SROW + lc0], a1p + (k0));                 \
        cp_async16(&Bs[stage][lr0 * SROW + lc0], b0p + (k0));                 \
        cp_async16(&Bs[stage][lr1 * SROW + lc0], b1p + (k0));                 \
    } while (0)

    LOAD_TILE(0, 0);
    cp_commit();

    for (int tile = 0; tile < T; tile++) {
        if (tile + 1 < T) LOAD_TILE((tile + 1) & 1, (tile + 1) * 16);
        cp_commit();
        cp_wait1();
        __syncthreads();

        const float* as = As[tile & 1];
        const float* bs = Bs[tile & 1];

#pragma unroll
        for (int ks = 0; ks < 2; ks++) {
            uint32_t af[4][4];
#pragma unroll
            for (int mt = 0; mt < 4; mt++) {
                int m0 = wm * 64 + mt * 16;
                int kk = ks * 8 + tq;
                af[mt][0] = f2tf(as[(m0 + g)     * SROW + kk]);
                af[mt][1] = f2tf(as[(m0 + g + 8) * SROW + kk]);
                af[mt][2] = f2tf(as[(m0 + g)     * SROW + kk + 4]);
                af[mt][3] = f2tf(as[(m0 + g + 8) * SROW + kk + 4]);
            }
            uint32_t bf[4][2];
#pragma unroll
            for (int nt = 0; nt < 4; nt++) {
                int n0 = wn * 32 + nt * 8;
                int kk = ks * 8 + tq;
                bf[nt][0] = f2tf(bs[(n0 + g) * SROW + kk]);
                bf[nt][1] = f2tf(bs[(n0 + g) * SROW + kk + 4]);
            }
#pragma unroll
            for (int mt = 0; mt < 4; mt++)
#pragma unroll
                for (int nt = 0; nt < 4; nt++)
                    mma_tf32(acc[mt][nt], af[mt], bf[nt]);
        }
        __syncthreads();
    }

#pragma unroll
    for (int mt = 0; mt < 4; mt++) {
        int r0 = mBase + wm * 64 + mt * 16 + g;
#pragma unroll
        for (int nt = 0; nt < 4; nt++) {
            int col = nBase + wn * 32 + nt * 8 + 2 * tq;
            float bv0 = bias[col], bv1 = bias[col + 1];
#pragma unroll
            for (int half = 0; half < 2; half++) {
                int row = half ? (r0 + 8) : r0;
                if (row >= M) continue;
                float v0 = acc[mt][nt][half * 2]     + bv0;
                float v1 = acc[mt][nt][half * 2 + 1] + bv1;
                if (EPI == 4) {
                    // scatter into head-major QKV: [which][nh][l][hd]
                    int which = col / Dm;
                    int rem = col - which * Dm;
                    int h = rem >> 6, hd = rem & 63;
                    int l = row >> 6, n = row & 63;
                    size_t dst = (((size_t)which * NH + (n * Hh + h)) * Lq + l) * HD + hd;
                    C[dst]     = v0;
                    C[dst + 1] = v1;
                } else {
                    size_t off = (size_t)row * Nc + col;
                    if (EPI == 2) {
                        v0 += res[off]; v1 += res[off + 1];
                    } else if (EPI == 3) {
                        float s0 = 1.0f / (1.0f + expf(-1.702f * v0));
                        float s1 = 1.0f / (1.0f + expf(-1.702f * v1));
                        v0 = res[off]     + v0 * s0;
                        v1 = res[off + 1] + v1 * s1;
                    }
                    C[off]     = v0;
                    C[off + 1] = v1;
                }
            }
        }
    }
}
#undef LOAD_TILE
#undef SROW

// ---------------- fused scores + softmax -----------------------------------
// grid (9, 768): block handles (nh, 32 l-rows). Full K head resident in smem.
// fp32 math; writes final softmaxed weights once.
#define SK 65
#define SCORES_SMEM ((Lq * SK + 32 * SK) * 4)
__global__ void __launch_bounds__(256) scores_softmax(const float* __restrict__ Qh,
                                                      const float* __restrict__ Kh,
                                                      float* __restrict__ w) {
    extern __shared__ float sm[];
    float* Ks = sm;                 // [257][SK]
    float* Qs = sm + Lq * SK;       // [32][SK]
    const int nh = blockIdx.y;
    const int lBase = blockIdx.x * 32;
    const int t = threadIdx.x;
    const int lane = t & 31, wid = t >> 5;

    // load full K head (257x64, contiguous)
    {
        const float* kp = Kh + (size_t)nh * LHD;
        for (int idx = t; idx < Lq * 16; idx += 256) {
            int r = idx >> 4, c4 = (idx & 15) * 4;
            float4 v = *(const float4*)(kp + r * HD + c4);
            float* d = Ks + r * SK + c4;
            d[0] = v.x; d[1] = v.y; d[2] = v.z; d[3] = v.w;
        }
    }
    // load Q chunk (32 rows, guarded)
    {
        const float* qp = Qh + (size_t)nh * LHD;
        for (int idx = t; idx < 32 * 16; idx += 256) {
            int r = idx >> 4, c4 = (idx & 15) * 4;
            int lg = lBase + r;
            float4 v = make_float4(0.f, 0.f, 0.f, 0.f);
            if (lg < Lq) v = *(const float4*)(qp + lg * HD + c4);
            float* d = Qs + r * SK + c4;
            d[0] = v.x; d[1] = v.y; d[2] = v.z; d[3] = v.w;
        }
    }
    __syncthreads();

    // warp wid owns rows l = wid*4 .. wid*4+3; lane owns m = j*32 + lane (j<9)
    int moff[9];
#pragma unroll
    for (int j = 0; j < 9; j++) {
        int m = j * 32 + lane;
        moff[j] = (m < Lq ? m : Lq - 1) * SK;   // clamp; invalid masked later
    }

    float acc[4][9];
#pragma unroll
    for (int i = 0; i < 4; i++)
#pragma unroll
        for (int j = 0; j < 9; j++) acc[i][j] = 0.0f;

    const float* qbase = Qs + wid * 4 * SK;
#pragma unroll 4
    for (int hd = 0; hd < HD; hd++) {
        float q0 = qbase[hd];
        float q1 = qbase[SK + hd];
        float q2 = qbase[2 * SK + hd];
        float q3 = qbase[3 * SK + hd];
        float kk[9];
#pragma unroll
        for (int j = 0; j < 9; j++) kk[j] = Ks[moff[j] + hd];
#pragma unroll
        for (int j = 0; j < 9; j++) {
            acc[0][j] = fmaf(q0, kk[j], acc[0][j]);
            acc[1][j] = fmaf(q1, kk[j], acc[1][j]);
            acc[2][j] = fmaf(q2, kk[j], acc[2][j]);
            acc[3][j] = fmaf(q3, kk[j], acc[3][j]);
        }
    }

    // per-row softmax (scale 1/8), write final weights
#pragma unroll
    for (int i = 0; i < 4; i++) {
        int row = lBase + wid * 4 + i;
        float mx = -INFINITY;
#pragma unroll
        for (int j = 0; j < 9; j++) {
            bool valid = (j * 32 + lane) < Lq;
            acc[i][j] = valid ? acc[i][j] * 0.125f : -INFINITY;
            mx = fmaxf(mx, acc[i][j]);
        }
#pragma unroll
        for (int off = 16; off > 0; off >>= 1)
            mx = fmaxf(mx, __shfl_xor_sync(0xffffffffu, mx, off));
        float s = 0.0f;
#pragma unroll
        for (int j = 0; j < 9; j++) {
            acc[i][j] = expf(acc[i][j] - mx);   // invalid -> exp(-inf)=0
            s += acc[i][j];
        }
#pragma unroll
        for (int off = 16; off > 0; off >>= 1)
            s += __shfl_xor_sync(0xffffffffu, s, off);
        float inv = 1.0f / s;
        if (row < Lq) {
            float* wr = w + ((size_t)nh * Lq + row) * Lq;
#pragma unroll
            for (int j = 0; j < 9; j++) {
                int m = j * 32 + lane;
                if (m < Lq) wr[m] = acc[i][j] * inv;
            }
        }
    }
}

// ---------------- attn = weights @ V (V head resident) ---------------------
// grid (9, 768): block handles (nh, 32 l-rows). Vs[257][SV], Ws[32][SW] smem.
#define SV 68
#define SW 260
#define ATTNV_SMEM ((Lq * SV + 32 * SW) * 4)
__global__ void __launch_bounds__(256) attnv2(const float* __restrict__ w,
                                              const float* __restrict__ Vh,
                                              float* __restrict__ out) {
    extern __shared__ float sm[];
    float* Vs = sm;                 // [257][SV], 16B-aligned rows
    float* Ws = sm + Lq * SV;       // [32][SW]
    const int nh = blockIdx.y;
    const int n = nh / Hh, h = nh % Hh;
    const int lBase = blockIdx.x * 32;
    const int t = threadIdx.x;

    // load full V head
    {
        const float* vp = Vh + (size_t)nh * LHD;
        for (int idx = t; idx < Lq * 16; idx += 256) {
            int r = idx >> 4, c4 = (idx & 15) * 4;
            float4 v = *(const float4*)(vp + r * HD + c4);
            *(float4*)(Vs + r * SV + c4) = v;
        }
    }
    // load weights chunk 32x257 (guarded rows)
    {
        for (int idx = t; idx < 32 * Lq; idx += 256) {
            int r = idx / Lq, c = idx - r * Lq;
            int lg = lBase + r;
            Ws[r * SW + c] = (lg < Lq)
                ? w[((size_t)nh * Lq + lg) * Lq + c] : 0.0f;
        }
    }
    __syncthreads();

    const int l = t >> 3;
    const int hb = (t & 7) * 8;
    const float* wrow = Ws + l * SW;

    float a0 = 0, a1 = 0, a2 = 0, a3 = 0, a4 = 0, a5 = 0, a6 = 0, a7 = 0;
#pragma unroll 4
    for (int m = 0; m < Lq; m++) {
        float wv = wrow[m];
        float4 v0 = *(const float4*)(Vs + m * SV + hb);
        float4 v1 = *(const float4*)(Vs + m * SV + hb + 4);
        a0 = fmaf(wv, v0.x, a0); a1 = fmaf(wv, v0.y, a1);
        a2 = fmaf(wv, v0.z, a2); a3 = fmaf(wv, v0.w, a3);
        a4 = fmaf(wv, v1.x, a4); a5 = fmaf(wv, v1.y, a5);
        a6 = fmaf(wv, v1.z, a6); a7 = fmaf(wv, v1.w, a7);
    }

    int lg = lBase + l;
    if (lg < Lq) {
        float* p = out + ((size_t)lg * Nb + n) * Dm + h * HD + hb;
        p[0] = a0; p[1] = a1; p[2] = a2; p[3] = a3;
        p[4] = a4; p[5] = a5; p[6] = a6; p[7] = a7;
    }
}

// ---------------------------------------------------------------------------
extern "C" void kernel_launch(void* const* d_in, const int* in_sizes, int n_in,
                              void* d_out, int out_size) {
    const float* x          = (const float*)d_in[0];
    const float* in_proj_w  = (const float*)d_in[1];
    const float* in_proj_b  = (const float*)d_in[2];
    const float* out_proj_w = (const float*)d_in[3];
    const float* out_proj_b = (const float*)d_in[4];
    const float* ln1_g      = (const float*)d_in[5];
    const float* ln1_b      = (const float*)d_in[6];
    const float* ln2_g      = (const float*)d_in[7];
    const float* ln2_b      = (const float*)d_in[8];
    const float* fc_w       = (const float*)d_in[9];
    const float* fc_b       = (const float*)d_in[10];

    float* out_x = (float*)d_out;
    float* out_w = (float*)d_out + X_ELEMS;

    // raise dynamic smem limits (idempotent, not a stream op)
    cudaFuncSetAttribute(scores_softmax, cudaFuncAttributeMaxDynamicSharedMemorySize, SCORES_SMEM);
    cudaFuncSetAttribute(attnv2,         cudaFuncAttributeMaxDynamicSharedMemorySize, ATTNV_SMEM);

    float* h    = g_h;
    float* qkvh = g_qkv;                 // head-major [which][nh][l][hd]
    float* attn = g_attn;
    float* x1   = g_x1;

    const int mGrid = (Mrows + 127) / 128;   // 129
    const int lGrid = (Lq + 31) / 32;        // 9

    // 1) LN1
    ln_kernel<<<Mrows, 256>>>(x, ln1_g, ln1_b, h);

    // 2) qkv = h @ W_in^T + b, scattered into head-major Q/K/V
    {
        dim3 grid(D3 / 128, mGrid);
        gemm_tc<4><<<grid, 256>>>(h, in_proj_w, in_proj_b, nullptr, qkvh, Dm, D3, Mrows);
    }

    // 3) fused scores + softmax -> weights output
    {
        dim3 grid(lGrid, NH);
        scores_softmax<<<grid, 256, SCORES_SMEM>>>(qkvh, qkvh + X_ELEMS, out_w);
    }

    // 4) attn = weights @ V
    {
        dim3 grid(lGrid, NH);
        attnv2<<<grid, 256, ATTNV_SMEM>>>(out_w, qkvh + 2 * X_ELEMS, attn);
    }

    // 5) x1 = x + attn @ W_out^T + b
    {
        dim3 grid(Dm / 128, mGrid);
        gemm_tc<2><<<grid, 256>>>(attn, out_proj_w, out_proj_b, x, x1, Dm, Dm, Mrows);
    }

    // 6) LN2
    ln_kernel<<<Mrows, 256>>>(x1, ln2_g, ln2_b, h);

    // 7) out = x1 + quick_gelu(h @ fc_w^T + fc_b)
    {
        dim3 grid(Dm / 128, mGrid);
        gemm_tc<3><<<grid, 256>>>(h, fc_w, fc_b, x1, out_x, Dm, Dm, Mrows);
    }
}